// round 9
// baseline (speedup 1.0000x reference)
#include <cuda_runtime.h>
#include <cuda_bf16.h>
#include <cstdint>

#define B 4
#define S 2048
#define H 4
#define DH 48
#define D 192
#define NEG_INF -1000000000.0f

// Scratch
__device__ float g_ctx[B*S*D];
__device__ float g_Linv[B*H*S];
__device__ float g_WT[4][D*D];                 // pre-transposed weights [k][j]
__device__ __nv_bfloat16 g_qh[B*H*S*DH];
__device__ __nv_bfloat16 g_ql[B*H*S*DH];
__device__ __nv_bfloat16 g_kh[B*H*S*DH];
__device__ __nv_bfloat16 g_kl[B*H*S*DH];
__device__ __nv_bfloat16 g_vh[B*H*S*DH];
__device__ __nv_bfloat16 g_vl[B*H*S*DH];
__device__ __nv_bfloat16 g_Eh[(size_t)B*H*S*S];  // 128MB exp(logits) hi
__device__ __nv_bfloat16 g_El[(size_t)B*H*S*S];  // 128MB exp(logits) lo

// ---------- packed fp32x2 helpers ----------
__device__ __forceinline__ unsigned long long pack2(float x, float y) {
    unsigned long long r;
    asm("mov.b64 %0, {%1,%2};" : "=l"(r) : "f"(x), "f"(y));
    return r;
}
__device__ __forceinline__ void unpack2(unsigned long long v, float& x, float& y) {
    asm("mov.b64 {%0,%1}, %2;" : "=f"(x), "=f"(y) : "l"(v));
}
__device__ __forceinline__ void ffma2(unsigned long long& d, unsigned long long a, unsigned long long b) {
    asm("fma.rn.f32x2 %0, %1, %2, %0;" : "+l"(d) : "l"(a), "l"(b));
}

// ---------- fast exp on the FMA pipe (no MUFU) ----------
// exp(x) = 2^(x*log2e); magic-number round, degree-5 Taylor for 2^f on [-.5,.5]
// rel err ~2.4e-6. Masked (-1e9) clamps to 2^-126 ~ 0.
__device__ __forceinline__ float fexp(float x) {
    float y = fmaxf(x * 1.44269504f, -126.0f);
    float t = y + 12582912.0f;                 // 1.5*2^23
    float f = y - (t - 12582912.0f);
    int   e = __float_as_int(t) - 0x4B400000;  // round(y) as int
    float s = __int_as_float((e + 127) << 23); // 2^round(y)
    float p =              1.3333558e-3f;
    p = fmaf(p, f, 9.6181291e-3f);
    p = fmaf(p, f, 5.5504109e-2f);
    p = fmaf(p, f, 2.4022651e-1f);
    p = fmaf(p, f, 6.9314718e-1f);
    p = fmaf(p, f, 1.0f);
    return p * s;
}

// ---------- cp.async helpers ----------
__device__ __forceinline__ void cp16(uint32_t saddr, const void* gptr) {
    asm volatile("cp.async.cg.shared.global [%0], [%1], 16;" :: "r"(saddr), "l"(gptr));
}
__device__ __forceinline__ void cp_commit() { asm volatile("cp.async.commit_group;"); }
__device__ __forceinline__ void cp_wait1()  { asm volatile("cp.async.wait_group 1;"); }
__device__ __forceinline__ void cp_wait0()  { asm volatile("cp.async.wait_group 0;"); }
__device__ __forceinline__ uint32_t cvta_s(const void* p) {
    return (uint32_t)__cvta_generic_to_shared(p);
}

// ---------- mma.sync / ldmatrix helpers ----------
__device__ __forceinline__ void ldsm4(uint32_t addr, uint32_t* r) {
    asm volatile("ldmatrix.sync.aligned.m8n8.x4.shared.b16 {%0,%1,%2,%3}, [%4];"
                 : "=r"(r[0]), "=r"(r[1]), "=r"(r[2]), "=r"(r[3]) : "r"(addr));
}
__device__ __forceinline__ void ldsm4t(uint32_t addr, uint32_t* r) {
    asm volatile("ldmatrix.sync.aligned.m8n8.x4.trans.shared.b16 {%0,%1,%2,%3}, [%4];"
                 : "=r"(r[0]), "=r"(r[1]), "=r"(r[2]), "=r"(r[3]) : "r"(addr));
}
__device__ __forceinline__ void ldsm2t(uint32_t addr, uint32_t* r) {
    asm volatile("ldmatrix.sync.aligned.m8n8.x2.trans.shared.b16 {%0,%1}, [%2];"
                 : "=r"(r[0]), "=r"(r[1]) : "r"(addr));
}
__device__ __forceinline__ void mma16816(float* c, const uint32_t* a, const uint32_t* b) {
    asm volatile("mma.sync.aligned.m16n8k16.row.col.f32.bf16.bf16.f32 "
                 "{%0,%1,%2,%3}, {%4,%5,%6,%7}, {%8,%9}, {%0,%1,%2,%3};"
                 : "+f"(c[0]), "+f"(c[1]), "+f"(c[2]), "+f"(c[3])
                 : "r"(a[0]), "r"(a[1]), "r"(a[2]), "r"(a[3]), "r"(b[0]), "r"(b[1]));
}

// ---------- weight transpose ----------
__global__ void transpose_w(const float* __restrict__ W0, const float* __restrict__ W1,
                            const float* __restrict__ W2, const float* __restrict__ W3) {
    __shared__ float tile[32][33];
    const float* W = (blockIdx.z == 0) ? W0 : (blockIdx.z == 1) ? W1 : (blockIdx.z == 2) ? W2 : W3;
    float* WT = g_WT[blockIdx.z];
    int x = blockIdx.x*32 + threadIdx.x;
    int y = blockIdx.y*32 + threadIdx.y;
    #pragma unroll
    for (int j = 0; j < 32; j += 8)
        tile[threadIdx.y + j][threadIdx.x] = W[(y + j)*D + x];
    __syncthreads();
    int x2 = blockIdx.y*32 + threadIdx.x;
    int y2 = blockIdx.x*32 + threadIdx.y;
    #pragma unroll
    for (int j = 0; j < 32; j += 8)
        WT[(y2 + j)*D + x2] = tile[threadIdx.x][threadIdx.y + j];
}

// ---------- projection core ----------
template<bool BF16OUT>
__device__ __forceinline__ void proj_core(const float* __restrict__ X,
                                          const float* __restrict__ WT,
                                          float* __restrict__ Yf,
                                          __nv_bfloat16* __restrict__ Yh,
                                          __nv_bfloat16* __restrict__ Yl,
                                          int r0) {
    __shared__ float sXT[192*33];
    const int tid = threadIdx.x;
    const int w = tid >> 5, lane = tid & 31;

    #pragma unroll
    for (int k = 0; k < 12; k++) {
        int idx = tid + k*128;
        int r = idx / 48, c = idx % 48;
        float4 v = *reinterpret_cast<const float4*>(X + (size_t)(r0 + r)*D + 4*c);
        sXT[(4*c+0)*33 + r] = v.x;
        sXT[(4*c+1)*33 + r] = v.y;
        sXT[(4*c+2)*33 + r] = v.z;
        sXT[(4*c+3)*33 + r] = v.w;
    }
    __syncthreads();

    unsigned long long acc[8][3];
    #pragma unroll
    for (int i = 0; i < 8; i++)
        #pragma unroll
        for (int p = 0; p < 3; p++) acc[i][p] = 0ull;

    #pragma unroll 2
    for (int k = 0; k < 192; k++) {
        const unsigned long long* wrow =
            reinterpret_cast<const unsigned long long*>(WT + k*D + lane*6);
        unsigned long long w0 = wrow[0], w1 = wrow[1], w2 = wrow[2];
        #pragma unroll
        for (int i = 0; i < 8; i++) {
            float xv = sXT[k*33 + w*8 + i];
            unsigned long long x2 = pack2(xv, xv);
            ffma2(acc[i][0], x2, w0);
            ffma2(acc[i][1], x2, w1);
            ffma2(acc[i][2], x2, w2);
        }
    }
    #pragma unroll
    for (int i = 0; i < 8; i++) {
        const int row = r0 + w*8 + i;      // b*S + s
        if (BF16OUT) {
            const int bb = row >> 11, s = row & 2047;
            const int hh = lane >> 3, c0 = (lane & 7)*6;
            size_t base = ((size_t)(bb*H + hh)*S + s)*DH + c0;
            #pragma unroll
            for (int m = 0; m < 3; m++) {
                float x, y; unpack2(acc[i][m], x, y);
                __nv_bfloat16 hx = __float2bfloat16(x);
                __nv_bfloat16 hy = __float2bfloat16(y);
                float lx = x - __bfloat162float(hx);
                float ly = y - __bfloat162float(hy);
                __nv_bfloat162 hv; hv.x = hx; hv.y = hy;
                __nv_bfloat162 lv; lv.x = __float2bfloat16(lx); lv.y = __float2bfloat16(ly);
                *reinterpret_cast<__nv_bfloat162*>(Yh + base + 2*m) = hv;
                *reinterpret_cast<__nv_bfloat162*>(Yl + base + 2*m) = lv;
            }
        } else {
            unsigned long long* dst =
                reinterpret_cast<unsigned long long*>(Yf + (size_t)row*D + lane*6);
            dst[0] = acc[i][0]; dst[1] = acc[i][1]; dst[2] = acc[i][2];
        }
    }
}

__global__ __launch_bounds__(128, 4) void proj3_kernel(const float* __restrict__ Xq,
                                                       const float* __restrict__ Xk,
                                                       const float* __restrict__ Xv) {
    const int which = blockIdx.y;
    const int r0 = blockIdx.x * 32;
    if (which == 2)      proj_core<true >(Xv, g_WT[2], nullptr, g_vh, g_vl, r0);
    else if (which == 0) proj_core<true >(Xq, g_WT[0], nullptr, g_qh, g_ql, r0);
    else                 proj_core<true >(Xk, g_WT[1], nullptr, g_kh, g_kl, r0);
}

__global__ __launch_bounds__(128, 4) void proj1_kernel(const float* __restrict__ X,
                                                       float* __restrict__ Y) {
    proj_core<false>(X, g_WT[3], Y, nullptr, nullptr, blockIdx.x * 32);
}

// ============================================================================
// logits_mma (R8 structure; exp moved off MUFU onto the FMA pipe)
// ============================================================================
#define OFF_QH 0
#define OFF_QL 8192
#define OFF_KH 16384
#define OFF_KL 49152
#define OFF_SUM 81920
#define SMEM_LG (OFF_SUM + 64*4*4)

__global__ __launch_bounds__(256, 2) void logits_mma(const int* __restrict__ gmask,
                                                     const float* __restrict__ gbias) {
    extern __shared__ char smem[];
    const uint32_t sb = cvta_s(smem);
    float (*sums)[4] = reinterpret_cast<float(*)[4]>(smem + OFF_SUM);
    const int tid = threadIdx.x;
    const int warp = tid >> 5, lane = tid & 31;
    const int bh = blockIdx.x;
    const int b  = bh >> 2, h = bh & 3;
    const int q0 = blockIdx.y * 64;
    const int qw = (warp >> 2) * 32;
    const int jw = (warp & 3) * 32;

    {
        const __nv_bfloat16* qh = g_qh + ((size_t)bh*S + q0)*DH;
        const __nv_bfloat16* ql = g_ql + ((size_t)bh*S + q0)*DH;
        #pragma unroll
        for (int k = 0; k < 2; k++) {
            int idx = tid + k*256;
            if (idx < 384) {
                int r = idx / 6, c = idx % 6;
                uint32_t off = r*128 + ((c ^ (r&7))<<4);
                cp16(sb + OFF_QH + off, qh + r*DH + c*8);
                cp16(sb + OFF_QL + off, ql + r*DH + c*8);
            }
        }
        const __nv_bfloat16* kh = g_kh + (size_t)bh*S*DH;
        const __nv_bfloat16* kl = g_kl + (size_t)bh*S*DH;
        #pragma unroll
        for (int k = 0; k < 3; k++) {
            int idx = tid + k*256;
            int r = idx / 6, c = idx % 6;
            uint32_t off = r*128 + ((c ^ (r&7))<<4);
            cp16(sb + OFF_KH + off, kh + r*DH + c*8);
            cp16(sb + OFF_KL + off, kl + r*DH + c*8);
        }
        cp_commit();
    }
    cp_wait0();
    __syncthreads();

    uint32_t ah[2][3][4];
    #pragma unroll
    for (int mi = 0; mi < 2; mi++)
        #pragma unroll
        for (int ks = 0; ks < 3; ks++) {
            int r = qw + mi*16 + (lane & 7) + ((lane >> 3) & 1)*8;
            int c = ks*2 + (lane >> 4);
            ldsm4(sb + OFF_QH + r*128 + ((c ^ (r&7))<<4), ah[mi][ks]);
        }

    float lsum[4] = {0.f, 0.f, 0.f, 0.f};

    for (int jt = 0; jt < 16; jt++) {
        const uint32_t kbH = sb + OFF_KH + (jt & 1)*16384;
        const uint32_t kbL = sb + OFF_KL + (jt & 1)*16384;

        if (jt + 1 < 16) {
            const uint32_t nH = sb + OFF_KH + ((jt+1) & 1)*16384;
            const uint32_t nL = sb + OFF_KL + ((jt+1) & 1)*16384;
            const __nv_bfloat16* kh = g_kh + ((size_t)bh*S + (jt+1)*128)*DH;
            const __nv_bfloat16* kl = g_kl + ((size_t)bh*S + (jt+1)*128)*DH;
            #pragma unroll
            for (int k = 0; k < 3; k++) {
                int idx = tid + k*256;
                int r = idx / 6, c = idx % 6;
                uint32_t off = r*128 + ((c ^ (r&7))<<4);
                cp16(nH + off, kh + r*DH + c*8);
                cp16(nL + off, kl + r*DH + c*8);
            }
            cp_commit();
        }

        float acc[2][4][4];
        #pragma unroll
        for (int mi = 0; mi < 2; mi++)
            #pragma unroll
            for (int nj = 0; nj < 4; nj++)
                #pragma unroll
                for (int p = 0; p < 4; p++) acc[mi][nj][p] = 0.f;

        #pragma unroll
        for (int ks = 0; ks < 3; ks++) {
            uint32_t bhf[2][4], blf[2][4], alf[2][4];
            #pragma unroll
            for (int jj = 0; jj < 2; jj++) {
                int r = jw + jj*16 + (lane & 7) + (lane >> 4)*8;
                int c = ks*2 + ((lane >> 3) & 1);
                uint32_t off = r*128 + ((c ^ (r&7))<<4);
                ldsm4(kbH + off, bhf[jj]);
                ldsm4(kbL + off, blf[jj]);
            }
            #pragma unroll
            for (int mi = 0; mi < 2; mi++) {
                int r = qw + mi*16 + (lane & 7) + ((lane >> 3) & 1)*8;
                int c = ks*2 + (lane >> 4);
                ldsm4(sb + OFF_QL + r*128 + ((c ^ (r&7))<<4), alf[mi]);
            }
            #pragma unroll
            for (int mi = 0; mi < 2; mi++)
                #pragma unroll
                for (int jj = 0; jj < 2; jj++)
                    #pragma unroll
                    for (int sub = 0; sub < 2; sub++) {
                        float* a = acc[mi][jj*2 + sub];
                        mma16816(a, ah[mi][ks], &bhf[jj][sub*2]);
                        mma16816(a, ah[mi][ks], &blf[jj][sub*2]);
                        mma16816(a, alf[mi],    &bhf[jj][sub*2]);
                    }
        }
        __syncthreads();

        const int jbase = jt*128 + jw + (lane & 3)*2;
        #pragma unroll
        for (int mi = 0; mi < 2; mi++)
            #pragma unroll
            for (int h2 = 0; h2 < 2; h2++) {
                const int qrow = q0 + qw + mi*16 + h2*8 + (lane >> 2);
                const int*   mrow = gmask + (size_t)(b*S + qrow)*S + jbase;
                const float* brow = gbias + (size_t)(h*S + qrow)*S + jbase;
                __nv_bfloat16* ehrow = g_Eh + ((size_t)bh*S + qrow)*S + jbase;
                __nv_bfloat16* elrow = g_El + ((size_t)bh*S + qrow)*S + jbase;
                float ls = 0.f;
                #pragma unroll
                for (int nj = 0; nj < 4; nj++) {
                    int2   mv = *reinterpret_cast<const int2*>(mrow + nj*8);
                    float2 bv = *reinterpret_cast<const float2*>(brow + nj*8);
                    float e0 = fexp(mv.x ? acc[mi][nj][h2*2+0] + bv.x : NEG_INF);
                    float e1 = fexp(mv.y ? acc[mi][nj][h2*2+1] + bv.y : NEG_INF);
                    __nv_bfloat16 eh0 = __float2bfloat16(e0);
                    __nv_bfloat16 eh1 = __float2bfloat16(e1);
                    __nv_bfloat162 hv; hv.x = eh0; hv.y = eh1;
                    __nv_bfloat162 lv;
                    lv.x = __float2bfloat16(e0 - __bfloat162float(eh0));
                    lv.y = __float2bfloat16(e1 - __bfloat162float(eh1));
                    *reinterpret_cast<__nv_bfloat162*>(ehrow + nj*8) = hv;
                    *reinterpret_cast<__nv_bfloat162*>(elrow + nj*8) = lv;
                    ls += e0 + e1;
                }
                lsum[mi*2 + h2] += ls;
            }

        cp_wait0();
    }

    #pragma unroll
    for (int k = 0; k < 4; k++) {
        float v = lsum[k];
        v += __shfl_xor_sync(0xffffffffu, v, 1);
        v += __shfl_xor_sync(0xffffffffu, v, 2);
        if ((lane & 3) == 0)
            sums[qw + (k >> 1)*16 + (k & 1)*8 + (lane >> 2)][warp & 3] = v;
    }
    __syncthreads();
    if (tid < 64) {
        float L = sums[tid][0] + sums[tid][1] + sums[tid][2] + sums[tid][3];
        g_Linv[(size_t)bh*S + q0 + tid] = 1.0f / L;
    }
}

// ============================================================================
// pv_mma: q-tile 32, 2 CTAs/SM (smem 105KB, <=128 regs target).
// 8 warps = (q-sub 16 x2) x (d-half 24 x2) x (ks-half x2); ks-halves reduced
// through smem at the end. V smem rows strided 112B (7x16B, 7 coprime 8 ->
// ldmatrix phases conflict-free, no padding waste).
// ============================================================================
#define PM_OFF_LINV 16896                 // after mean [32][132] floats
#define PM_OFF_TILE 17408
#define PM_EH 0                           // 32 rows x 256B
#define PM_EL 8192
#define PM_VH 16384                       // 128 rows x 112B
#define PM_VL 30720
#define PM_BUF 45056
#define SMEM_PV (PM_OFF_TILE + 2*PM_BUF)  // 107520

__global__ __launch_bounds__(256, 2) void pv_mma(float* __restrict__ om) {
    extern __shared__ char smem[];
    const uint32_t sb = cvta_s(smem);
    float* sMean  = reinterpret_cast<float*>(smem);                 // [32][132]
    float* sLinvf = reinterpret_cast<float*>(smem + PM_OFF_LINV);   // [4][32]
    float* sRed   = reinterpret_cast<float*>(smem + PM_OFF_TILE);   // end-of-kernel O staging
    const int tid = threadIdx.x;
    const int warp = tid >> 5, lane = tid & 31;
    const int b  = blockIdx.x;
    const int q0 = blockIdx.y * 32;
    const int q0w = ((warp >> 2) & 1) * 16;
    const int wd  = (warp >> 1) & 1;
    const int kh2 = warp & 1;
    const int cV  = wd * 3;               // V 16B-chunk base (d0 = wd*24)

    if (tid < 128) sLinvf[tid] = g_Linv[(size_t)(b*H + (tid>>5))*S + q0 + (tid & 31)];

    auto load_stage = [&](int jt, int hh, uint32_t bufb) {
        const int bhl = b*H + hh;
        const __nv_bfloat16* ehp = g_Eh + ((size_t)bhl*S + q0)*S + jt*128;
        const __nv_bfloat16* elp = g_El + ((size_t)bhl*S + q0)*S + jt*128;
        #pragma unroll
        for (int k = 0; k < 2; k++) {
            int idx = tid + k*256;           // 512 chunks (32 rows x 16)
            int r = idx >> 4, cj = idx & 15;
            uint32_t off = r*256 + ((cj ^ (r&7))<<4);
            cp16(bufb + PM_EH + off, ehp + (size_t)r*S + cj*8);
            cp16(bufb + PM_EL + off, elp + (size_t)r*S + cj*8);
        }
        const __nv_bfloat16* vhp = g_vh + ((size_t)bhl*S + jt*128)*DH;
        const __nv_bfloat16* vlp = g_vl + ((size_t)bhl*S + jt*128)*DH;
        #pragma unroll
        for (int k = 0; k < 3; k++) {
            int idx = tid + k*256;           // 768 chunks (128 rows x 6)
            int r = idx / 6, c = idx % 6;
            uint32_t off = r*112 + c*16;
            cp16(bufb + PM_VH + off, vhp + r*DH + c*8);
            cp16(bufb + PM_VL + off, vlp + r*DH + c*8);
        }
    };

    load_stage(0, 0, sb + PM_OFF_TILE);
    cp_commit();
    __syncthreads();

    float acc[4][3][4];
    #pragma unroll
    for (int hh = 0; hh < 4; hh++)
        #pragma unroll
        for (int nt = 0; nt < 3; nt++)
            #pragma unroll
            for (int p = 0; p < 4; p++) acc[hh][nt][p] = 0.f;

    for (int jt = 0; jt < 16; jt++) {
        #pragma unroll
        for (int hh = 0; hh < 4; hh++) {
            const int st = jt*4 + hh;
            if (st + 1 < 64) {
                const int njt = (hh == 3) ? jt + 1 : jt;
                const int nhh = (hh == 3) ? 0 : hh + 1;
                load_stage(njt, nhh, sb + PM_OFF_TILE + ((st+1) & 1)*PM_BUF);
                cp_commit();
                cp_wait1();
            } else {
                cp_wait0();
            }
            __syncthreads();
            const uint32_t tb = sb + PM_OFF_TILE + (st & 1)*PM_BUF;
            const char*   tbp = smem + PM_OFF_TILE + (st & 1)*PM_BUF;

            // head-mean accumulation: (Eh+El)*Linv into sMean
            #pragma unroll
            for (int k = 0; k < 2; k++) {
                int idx = tid + k*256;
                int q = idx >> 4, cj = idx & 15;
                uint32_t eoff = q*256 + ((cj ^ (q&7))<<4);
                uint4 uh = *reinterpret_cast<const uint4*>(tbp + PM_EH + eoff);
                uint4 ul = *reinterpret_cast<const uint4*>(tbp + PM_EL + eoff);
                float linv = sLinvf[hh*32 + q];
                float2 f0 = __bfloat1622float2(*reinterpret_cast<__nv_bfloat162*>(&uh.x));
                float2 f1 = __bfloat1622float2(*reinterpret_cast<__nv_bfloat162*>(&uh.y));
                float2 f2 = __bfloat1622float2(*reinterpret_cast<__nv_bfloat162*>(&uh.z));
                float2 f3 = __bfloat1622float2(*reinterpret_cast<__nv_bfloat162*>(&uh.w));
                float2 g0 = __bfloat1622float2(*reinterpret_cast<__nv_bfloat162*>(&ul.x));
                float2 g1 = __bfloat1622float2(*reinterpret_cast<__nv_bfloat162*>(&ul.y));
                float2 g2 = __bfloat1622float2(*reinterpret_cast<__nv_bfloat162*>(&ul.z));
                float2 g3 = __bfloat1622float2(*reinterpret_cast<__nv_bfloat162*>(&ul.w));
                float* mp = sMean + q*132 + cj*8;
                if (hh == 0) {
                    float4 m0, m1;
                    m0.x = (f0.x+g0.x)*linv; m0.y = (f0.y+g0.y)*linv;
                    m0.z = (f1.x+g1.x)*linv; m0.w = (f1.y+g1.y)*linv;
                    m1.x = (f2.x+g2.x)*linv; m1.y = (f2.y+g2.y)*linv;
                    m1.z = (f3.x+g3.x)*linv; m1.w = (f3.y+g3.y)*linv;
                    *reinterpret_cast<float4*>(mp)     = m0;
                    *reinterpret_cast<float4*>(mp + 4) = m1;
                } else {
                    float4 m0 = *reinterpret_cast<float4*>(mp);
                    float4 m1 = *reinterpret_cast<float4*>(mp + 4);
                    m0.x += (f0.x+g0.x)*linv; m0.y += (f0.y+g0.y)*linv;
                    m0.z += (f1.x+g1.x)*linv; m0.w += (f1.y+g1.y)*linv;
                    m1.x += (f2.x+g2.x)*linv; m1.y += (f2.y+g2.y)*linv;
                    m1.z += (f3.x+g3.x)*linv; m1.w += (f3.y+g3.y)*linv;
                    *reinterpret_cast<float4*>(mp)     = m0;
                    *reinterpret_cast<float4*>(mp + 4) = m1;
                }
            }

            // MMA: A = E[q0w..+15][ks-half j], B = V[j][wd*24..+23]
            #pragma unroll
            for (int k = 0; k < 4; k++) {
                const int ks = kh2*4 + k;
                int ra = q0w + (lane & 15);
                int ca = ks*2 + (lane >> 4);
                uint32_t aoff = ra*256 + ((ca ^ (ra&7))<<4);
                uint32_t ahf[4], alf[4];
                ldsm4(tb + PM_EH + aoff, ahf);
                ldsm4(tb + PM_EL + aoff, alf);

                int rb = ks*16 + (lane & 15);
                uint32_t boff4 = rb*112 + (cV + (lane >> 4))*16;
                uint32_t bh4[4], bl4[4];
                ldsm4t(tb + PM_VH + boff4, bh4);
                ldsm4t(tb + PM_VL + boff4, bl4);
                uint32_t boff2 = rb*112 + (cV + 2)*16;
                uint32_t bh2[2], bl2[2];
                ldsm2t(tb + PM_VH + boff2, bh2);
                ldsm2t(tb + PM_VL + boff2, bl2);

                #pragma unroll
                for (int nt = 0; nt < 2; nt++) {
                    float* a = acc[hh][nt];
                    mma16816(a, ahf, &bh4[nt*2]);
                    mma16816(a, ahf, &bl4[nt*2]);
                    mma16816(a, alf, &bh4[nt*2]);
                }
                {
                    float* a = acc[hh][2];
                    mma16816(a, ahf, bh2);
                    mma16816(a, ahf, bl2);
                    mma16816(a, alf, bh2);
                }
            }

            if (hh == 3) {
                __syncthreads();
                #pragma unroll
                for (int k = 0; k < 4; k++) {
                    int idx = tid + k*256;
                    int q = idx >> 5, c4 = idx & 31;
                    float4 v = *reinterpret_cast<const float4*>(sMean + q*132 + c4*4);
                    float4 r; r.x = 0.25f*v.x; r.y = 0.25f*v.y; r.z = 0.25f*v.z; r.w = 0.25f*v.w;
                    *reinterpret_cast<float4*>(om + (size_t)(b*S + q0 + q)*S + jt*128 + c4*4) = r;
                }
            }
            __syncthreads();
        }
    }

    // reduce ks-halves: kh2=1 warps stage 48 floats each, kh2=0 adds + writes
    if (kh2 == 1) {
        float* dst = sRed + ((size_t)(warp >> 1)*32 + lane)*48;
        #pragma unroll
        for (int hh = 0; hh < 4; hh++)
            #pragma unroll
            for (int nt = 0; nt < 3; nt++)
                #pragma unroll
                for (int p = 0; p < 4; p++) dst[hh*12 + nt*4 + p] = acc[hh][nt][p];
    }
    __syncthreads();
    if (kh2 == 0) {
        const float* src = sRed + ((size_t)(warp >> 1)*32 + lane)*48;
        const int row0 = q0w + (lane >> 2);
        #pragma unroll
        for (int hh = 0; hh < 4; hh++) {
            const float l0 = sLinvf[hh*32 + row0];
            const float l1 = sLinvf[hh*32 + row0 + 8];
            #pragma unroll
            for (int nt = 0; nt < 3; nt++) {
                float a0 = acc[hh][nt][0] + src[hh*12 + nt*4 + 0];
                float a1 = acc[hh][nt][1] + src[hh*12 + nt*4 + 1];
                float a2 = acc[hh][nt][2] + src[hh*12 + nt*4 + 2];
                float a3 = acc[hh][nt][3] + src[hh*12 + nt*4 + 3];
                const int col = hh*48 + wd*24 + nt*8 + (lane & 3)*2;
                float2 o0; o0.x = a0*l0; o0.y = a1*l0;
                float2 o1; o1.x = a2*l1; o1.y = a3*l1;
                *reinterpret_cast<float2*>(g_ctx + (size_t)(b*S + q0 + row0)*D + col)     = o0;
                *reinterpret_cast<float2*>(g_ctx + (size_t)(b*S + q0 + row0 + 8)*D + col) = o1;
            }
        }
    }
}

extern "C" void kernel_launch(void* const* d_in, const int* in_sizes, int n_in,
                              void* d_out, int out_size) {
    (void)in_sizes; (void)n_in; (void)out_size;
    const float* query = (const float*)d_in[0];
    const float* key   = (const float*)d_in[1];
    const float* value = (const float*)d_in[2];
    const int*   mask  = (const int*)  d_in[3];
    const float* bias  = (const float*)d_in[4];
    const float* Wq    = (const float*)d_in[5];
    const float* Wk    = (const float*)d_in[6];
    const float* Wv    = (const float*)d_in[7];
    const float* Wo    = (const float*)d_in[8];

    float* out = (float*)d_out;                 // [B,S,D]
    float* om  = out + B*S*D;                   // [B,S,S] mean weights

    float *pctx;
    cudaGetSymbolAddress((void**)&pctx, g_ctx);

    cudaFuncSetAttribute(logits_mma, cudaFuncAttributeMaxDynamicSharedMemorySize, SMEM_LG);
    cudaFuncSetAttribute(pv_mma,     cudaFuncAttributeMaxDynamicSharedMemorySize, SMEM_PV);

    transpose_w<<<dim3(6,6,4), dim3(32,8)>>>(Wq, Wk, Wv, Wo);
    proj3_kernel<<<dim3(256,3), 128>>>(query, key, value);
    logits_mma<<<dim3(B*H, S/64), 256, SMEM_LG>>>(mask, bias);
    pv_mma<<<dim3(B, 64), 256, SMEM_PV>>>(om);
    proj1_kernel<<<dim3(256,1), 128>>>(pctx, out);
}

// round 10
// speedup vs baseline: 1.1314x; 1.1314x over previous
#include <cuda_runtime.h>
#include <cuda_bf16.h>
#include <cstdint>

#define B 4
#define S 2048
#define H 4
#define DH 48
#define D 192
#define NEG_INF -1000000000.0f

// Scratch
__device__ float g_ctx[B*S*D];
__device__ float g_Linv[B*H*S];
__device__ float g_WT[4][D*D];                 // pre-transposed weights [k][j]
__device__ __nv_bfloat16 g_qh[B*H*S*DH];
__device__ __nv_bfloat16 g_ql[B*H*S*DH];
__device__ __nv_bfloat16 g_kh[B*H*S*DH];
__device__ __nv_bfloat16 g_kl[B*H*S*DH];
__device__ __nv_bfloat16 g_vh[B*H*S*DH];
__device__ __nv_bfloat16 g_vl[B*H*S*DH];
// E stored j-PERMUTED (fragment-native): within each 32-j group,
// actual a = 2p + 8t + u  <->  virtual v = 8p + 2t + u.
__device__ __nv_bfloat16 g_Eh[(size_t)B*H*S*S];
__device__ __nv_bfloat16 g_El[(size_t)B*H*S*S];

// ---------- packed fp32x2 helpers ----------
__device__ __forceinline__ unsigned long long pack2(float x, float y) {
    unsigned long long r;
    asm("mov.b64 %0, {%1,%2};" : "=l"(r) : "f"(x), "f"(y));
    return r;
}
__device__ __forceinline__ void unpack2(unsigned long long v, float& x, float& y) {
    asm("mov.b64 {%0,%1}, %2;" : "=f"(x), "=f"(y) : "l"(v));
}
__device__ __forceinline__ void ffma2(unsigned long long& d, unsigned long long a, unsigned long long b) {
    asm("fma.rn.f32x2 %0, %1, %2, %0;" : "+l"(d) : "l"(a), "l"(b));
}

// ---------- fast exp on the FMA pipe ----------
__device__ __forceinline__ float fexp(float x) {
    float y = fmaxf(x * 1.44269504f, -126.0f);
    float t = y + 12582912.0f;
    float f = y - (t - 12582912.0f);
    int   e = __float_as_int(t) - 0x4B400000;
    float s = __int_as_float((e + 127) << 23);
    float p =              1.3333558e-3f;
    p = fmaf(p, f, 9.6181291e-3f);
    p = fmaf(p, f, 5.5504109e-2f);
    p = fmaf(p, f, 2.4022651e-1f);
    p = fmaf(p, f, 6.9314718e-1f);
    p = fmaf(p, f, 1.0f);
    return p * s;
}

// ---------- cp.async helpers ----------
__device__ __forceinline__ void cp16(uint32_t saddr, const void* gptr) {
    asm volatile("cp.async.cg.shared.global [%0], [%1], 16;" :: "r"(saddr), "l"(gptr));
}
__device__ __forceinline__ void cp_commit() { asm volatile("cp.async.commit_group;"); }
__device__ __forceinline__ void cp_wait1()  { asm volatile("cp.async.wait_group 1;"); }
__device__ __forceinline__ void cp_wait0()  { asm volatile("cp.async.wait_group 0;"); }
__device__ __forceinline__ uint32_t cvta_s(const void* p) {
    return (uint32_t)__cvta_generic_to_shared(p);
}

// ---------- mma.sync / ldmatrix helpers ----------
__device__ __forceinline__ void ldsm4(uint32_t addr, uint32_t* r) {
    asm volatile("ldmatrix.sync.aligned.m8n8.x4.shared.b16 {%0,%1,%2,%3}, [%4];"
                 : "=r"(r[0]), "=r"(r[1]), "=r"(r[2]), "=r"(r[3]) : "r"(addr));
}
__device__ __forceinline__ void ldsm4t(uint32_t addr, uint32_t* r) {
    asm volatile("ldmatrix.sync.aligned.m8n8.x4.trans.shared.b16 {%0,%1,%2,%3}, [%4];"
                 : "=r"(r[0]), "=r"(r[1]), "=r"(r[2]), "=r"(r[3]) : "r"(addr));
}
__device__ __forceinline__ void ldsm2t(uint32_t addr, uint32_t* r) {
    asm volatile("ldmatrix.sync.aligned.m8n8.x2.trans.shared.b16 {%0,%1}, [%2];"
                 : "=r"(r[0]), "=r"(r[1]) : "r"(addr));
}
__device__ __forceinline__ void mma16816(float* c, const uint32_t* a, const uint32_t* b) {
    asm volatile("mma.sync.aligned.m16n8k16.row.col.f32.bf16.bf16.f32 "
                 "{%0,%1,%2,%3}, {%4,%5,%6,%7}, {%8,%9}, {%0,%1,%2,%3};"
                 : "+f"(c[0]), "+f"(c[1]), "+f"(c[2]), "+f"(c[3])
                 : "r"(a[0]), "r"(a[1]), "r"(a[2]), "r"(a[3]), "r"(b[0]), "r"(b[1]));
}

// ---------- weight transpose ----------
__global__ void transpose_w(const float* __restrict__ W0, const float* __restrict__ W1,
                            const float* __restrict__ W2, const float* __restrict__ W3) {
    __shared__ float tile[32][33];
    const float* W = (blockIdx.z == 0) ? W0 : (blockIdx.z == 1) ? W1 : (blockIdx.z == 2) ? W2 : W3;
    float* WT = g_WT[blockIdx.z];
    int x = blockIdx.x*32 + threadIdx.x;
    int y = blockIdx.y*32 + threadIdx.y;
    #pragma unroll
    for (int j = 0; j < 32; j += 8)
        tile[threadIdx.y + j][threadIdx.x] = W[(y + j)*D + x];
    __syncthreads();
    int x2 = blockIdx.y*32 + threadIdx.x;
    int y2 = blockIdx.x*32 + threadIdx.y;
    #pragma unroll
    for (int j = 0; j < 32; j += 8)
        WT[(y2 + j)*D + x2] = tile[threadIdx.x][threadIdx.y + j];
}

// ---------- projection core ----------
template<bool BF16OUT>
__device__ __forceinline__ void proj_core(const float* __restrict__ X,
                                          const float* __restrict__ WT,
                                          float* __restrict__ Yf,
                                          __nv_bfloat16* __restrict__ Yh,
                                          __nv_bfloat16* __restrict__ Yl,
                                          int r0) {
    __shared__ float sXT[192*33];
    const int tid = threadIdx.x;
    const int w = tid >> 5, lane = tid & 31;

    #pragma unroll
    for (int k = 0; k < 12; k++) {
        int idx = tid + k*128;
        int r = idx / 48, c = idx % 48;
        float4 v = *reinterpret_cast<const float4*>(X + (size_t)(r0 + r)*D + 4*c);
        sXT[(4*c+0)*33 + r] = v.x;
        sXT[(4*c+1)*33 + r] = v.y;
        sXT[(4*c+2)*33 + r] = v.z;
        sXT[(4*c+3)*33 + r] = v.w;
    }
    __syncthreads();

    unsigned long long acc[8][3];
    #pragma unroll
    for (int i = 0; i < 8; i++)
        #pragma unroll
        for (int p = 0; p < 3; p++) acc[i][p] = 0ull;

    #pragma unroll 2
    for (int k = 0; k < 192; k++) {
        const unsigned long long* wrow =
            reinterpret_cast<const unsigned long long*>(WT + k*D + lane*6);
        unsigned long long w0 = wrow[0], w1 = wrow[1], w2 = wrow[2];
        #pragma unroll
        for (int i = 0; i < 8; i++) {
            float xv = sXT[k*33 + w*8 + i];
            unsigned long long x2 = pack2(xv, xv);
            ffma2(acc[i][0], x2, w0);
            ffma2(acc[i][1], x2, w1);
            ffma2(acc[i][2], x2, w2);
        }
    }
    #pragma unroll
    for (int i = 0; i < 8; i++) {
        const int row = r0 + w*8 + i;      // b*S + s
        if (BF16OUT) {
            const int bb = row >> 11, s = row & 2047;
            const int hh = lane >> 3, c0 = (lane & 7)*6;
            size_t base = ((size_t)(bb*H + hh)*S + s)*DH + c0;
            #pragma unroll
            for (int m = 0; m < 3; m++) {
                float x, y; unpack2(acc[i][m], x, y);
                __nv_bfloat16 hx = __float2bfloat16(x);
                __nv_bfloat16 hy = __float2bfloat16(y);
                float lx = x - __bfloat162float(hx);
                float ly = y - __bfloat162float(hy);
                __nv_bfloat162 hv; hv.x = hx; hv.y = hy;
                __nv_bfloat162 lv; lv.x = __float2bfloat16(lx); lv.y = __float2bfloat16(ly);
                *reinterpret_cast<__nv_bfloat162*>(Yh + base + 2*m) = hv;
                *reinterpret_cast<__nv_bfloat162*>(Yl + base + 2*m) = lv;
            }
        } else {
            unsigned long long* dst =
                reinterpret_cast<unsigned long long*>(Yf + (size_t)row*D + lane*6);
            dst[0] = acc[i][0]; dst[1] = acc[i][1]; dst[2] = acc[i][2];
        }
    }
}

__global__ __launch_bounds__(128, 4) void proj3_kernel(const float* __restrict__ Xq,
                                                       const float* __restrict__ Xk,
                                                       const float* __restrict__ Xv) {
    const int which = blockIdx.y;
    const int r0 = blockIdx.x * 32;
    if (which == 2)      proj_core<true >(Xv, g_WT[2], nullptr, g_vh, g_vl, r0);
    else if (which == 0) proj_core<true >(Xq, g_WT[0], nullptr, g_qh, g_ql, r0);
    else                 proj_core<true >(Xk, g_WT[1], nullptr, g_kh, g_kl, r0);
}

__global__ __launch_bounds__(128, 4) void proj1_kernel(const float* __restrict__ X,
                                                       float* __restrict__ Y) {
    proj_core<false>(X, g_WT[3], Y, nullptr, nullptr, blockIdx.x * 32);
}

// ============================================================================
// logits_mma: E stored as bf16 hi/lo in PERMUTED order — each thread packs its
// 8 fragment values into one uint4 (16B) -> 64B-contiguous quad stores, full
// 32B sectors (fix for the R8 half-sector regression).
// ============================================================================
#define OFF_QH 0
#define OFF_QL 8192
#define OFF_KH 16384
#define OFF_KL 49152
#define OFF_SUM 81920
#define SMEM_LG (OFF_SUM + 64*4*4)

__global__ __launch_bounds__(256, 2) void logits_mma(const int* __restrict__ gmask,
                                                     const float* __restrict__ gbias) {
    extern __shared__ char smem[];
    const uint32_t sb = cvta_s(smem);
    float (*sums)[4] = reinterpret_cast<float(*)[4]>(smem + OFF_SUM);
    const int tid = threadIdx.x;
    const int warp = tid >> 5, lane = tid & 31;
    const int bh = blockIdx.x;
    const int b  = bh >> 2, h = bh & 3;
    const int q0 = blockIdx.y * 64;
    const int qw = (warp >> 2) * 32;
    const int jw = (warp & 3) * 32;

    {
        const __nv_bfloat16* qh = g_qh + ((size_t)bh*S + q0)*DH;
        const __nv_bfloat16* ql = g_ql + ((size_t)bh*S + q0)*DH;
        #pragma unroll
        for (int k = 0; k < 2; k++) {
            int idx = tid + k*256;
            if (idx < 384) {
                int r = idx / 6, c = idx % 6;
                uint32_t off = r*128 + ((c ^ (r&7))<<4);
                cp16(sb + OFF_QH + off, qh + r*DH + c*8);
                cp16(sb + OFF_QL + off, ql + r*DH + c*8);
            }
        }
        const __nv_bfloat16* kh = g_kh + (size_t)bh*S*DH;
        const __nv_bfloat16* kl = g_kl + (size_t)bh*S*DH;
        #pragma unroll
        for (int k = 0; k < 3; k++) {
            int idx = tid + k*256;
            int r = idx / 6, c = idx % 6;
            uint32_t off = r*128 + ((c ^ (r&7))<<4);
            cp16(sb + OFF_KH + off, kh + r*DH + c*8);
            cp16(sb + OFF_KL + off, kl + r*DH + c*8);
        }
        cp_commit();
    }
    cp_wait0();
    __syncthreads();

    uint32_t ah[2][3][4];
    #pragma unroll
    for (int mi = 0; mi < 2; mi++)
        #pragma unroll
        for (int ks = 0; ks < 3; ks++) {
            int r = qw + mi*16 + (lane & 7) + ((lane >> 3) & 1)*8;
            int c = ks*2 + (lane >> 4);
            ldsm4(sb + OFF_QH + r*128 + ((c ^ (r&7))<<4), ah[mi][ks]);
        }

    float lsum[4] = {0.f, 0.f, 0.f, 0.f};

    for (int jt = 0; jt < 16; jt++) {
        const uint32_t kbH = sb + OFF_KH + (jt & 1)*16384;
        const uint32_t kbL = sb + OFF_KL + (jt & 1)*16384;

        if (jt + 1 < 16) {
            const uint32_t nH = sb + OFF_KH + ((jt+1) & 1)*16384;
            const uint32_t nL = sb + OFF_KL + ((jt+1) & 1)*16384;
            const __nv_bfloat16* kh = g_kh + ((size_t)bh*S + (jt+1)*128)*DH;
            const __nv_bfloat16* kl = g_kl + ((size_t)bh*S + (jt+1)*128)*DH;
            #pragma unroll
            for (int k = 0; k < 3; k++) {
                int idx = tid + k*256;
                int r = idx / 6, c = idx % 6;
                uint32_t off = r*128 + ((c ^ (r&7))<<4);
                cp16(nH + off, kh + r*DH + c*8);
                cp16(nL + off, kl + r*DH + c*8);
            }
            cp_commit();
        }

        float acc[2][4][4];
        #pragma unroll
        for (int mi = 0; mi < 2; mi++)
            #pragma unroll
            for (int nj = 0; nj < 4; nj++)
                #pragma unroll
                for (int p = 0; p < 4; p++) acc[mi][nj][p] = 0.f;

        #pragma unroll
        for (int ks = 0; ks < 3; ks++) {
            uint32_t bhf[2][4], blf[2][4], alf[2][4];
            #pragma unroll
            for (int jj = 0; jj < 2; jj++) {
                int r = jw + jj*16 + (lane & 7) + (lane >> 4)*8;
                int c = ks*2 + ((lane >> 3) & 1);
                uint32_t off = r*128 + ((c ^ (r&7))<<4);
                ldsm4(kbH + off, bhf[jj]);
                ldsm4(kbL + off, blf[jj]);
            }
            #pragma unroll
            for (int mi = 0; mi < 2; mi++) {
                int r = qw + mi*16 + (lane & 7) + ((lane >> 3) & 1)*8;
                int c = ks*2 + (lane >> 4);
                ldsm4(sb + OFF_QL + r*128 + ((c ^ (r&7))<<4), alf[mi]);
            }
            #pragma unroll
            for (int mi = 0; mi < 2; mi++)
                #pragma unroll
                for (int jj = 0; jj < 2; jj++)
                    #pragma unroll
                    for (int sub = 0; sub < 2; sub++) {
                        float* a = acc[mi][jj*2 + sub];
                        mma16816(a, ah[mi][ks], &bhf[jj][sub*2]);
                        mma16816(a, ah[mi][ks], &blf[jj][sub*2]);
                        mma16816(a, alf[mi],    &bhf[jj][sub*2]);
                    }
        }
        __syncthreads();

        // epilogue: mask/bias (actual-j), exp, packed uint4 stores (virtual-j)
        const int jbase  = jt*128 + jw + (lane & 3)*2;   // actual j base
        const int jvbase = jt*128 + jw + 8*(lane & 3);   // virtual (permuted)
        #pragma unroll
        for (int mi = 0; mi < 2; mi++)
            #pragma unroll
            for (int h2 = 0; h2 < 2; h2++) {
                const int qrow = q0 + qw + mi*16 + h2*8 + (lane >> 2);
                const int*   mrow = gmask + (size_t)(b*S + qrow)*S + jbase;
                const float* brow = gbias + (size_t)(h*S + qrow)*S + jbase;
                float ls = 0.f;
                uint32_t hw[4], lw[4];
                #pragma unroll
                for (int nj = 0; nj < 4; nj++) {
                    int2   mv = *reinterpret_cast<const int2*>(mrow + nj*8);
                    float2 bv = *reinterpret_cast<const float2*>(brow + nj*8);
                    float e0 = fexp(mv.x ? acc[mi][nj][h2*2+0] + bv.x : NEG_INF);
                    float e1 = fexp(mv.y ? acc[mi][nj][h2*2+1] + bv.y : NEG_INF);
                    __nv_bfloat162 hv;
                    hv.x = __float2bfloat16(e0);
                    hv.y = __float2bfloat16(e1);
                    __nv_bfloat162 lv;
                    lv.x = __float2bfloat16(e0 - __bfloat162float(hv.x));
                    lv.y = __float2bfloat16(e1 - __bfloat162float(hv.y));
                    hw[nj] = *reinterpret_cast<uint32_t*>(&hv);
                    lw[nj] = *reinterpret_cast<uint32_t*>(&lv);
                    ls += e0 + e1;
                }
                uint4 hq; hq.x = hw[0]; hq.y = hw[1]; hq.z = hw[2]; hq.w = hw[3];
                uint4 lq; lq.x = lw[0]; lq.y = lw[1]; lq.z = lw[2]; lq.w = lw[3];
                *reinterpret_cast<uint4*>(g_Eh + ((size_t)bh*S + qrow)*S + jvbase) = hq;
                *reinterpret_cast<uint4*>(g_El + ((size_t)bh*S + qrow)*S + jvbase) = lq;
                lsum[mi*2 + h2] += ls;
            }

        cp_wait0();
    }

    #pragma unroll
    for (int k = 0; k < 4; k++) {
        float v = lsum[k];
        v += __shfl_xor_sync(0xffffffffu, v, 1);
        v += __shfl_xor_sync(0xffffffffu, v, 2);
        if ((lane & 3) == 0)
            sums[qw + (k >> 1)*16 + (k & 1)*8 + (lane >> 2)][warp & 3] = v;
    }
    __syncthreads();
    if (tid < 64) {
        float L = sums[tid][0] + sums[tid][1] + sums[tid][2] + sums[tid][3];
        g_Linv[(size_t)bh*S + q0 + tid] = 1.0f / L;
    }
}

// ============================================================================
// pv_mma (R8 q-tile-64 version): V rows loaded at PERMUTED smem positions to
// match E's virtual j-order (k-dim permutation is contraction-invariant);
// head-mean output de-permuted on the om write.
// ============================================================================
#define PM_OFF_LINV 33792
#define PM_OFF_TILE 34816
#define PM_BUF 65536
#define PM_EH 0
#define PM_EL 16384
#define PM_VH 32768
#define PM_VL 49152
#define SMEM_PV (PM_OFF_TILE + 2*PM_BUF)

__global__ __launch_bounds__(256, 1) void pv_mma(float* __restrict__ om) {
    extern __shared__ char smem[];
    const uint32_t sb = cvta_s(smem);
    float* sMean  = reinterpret_cast<float*>(smem);                 // [64][132]
    float* sLinvf = reinterpret_cast<float*>(smem + PM_OFF_LINV);   // [4][64]
    const int tid = threadIdx.x;
    const int warp = tid >> 5, lane = tid & 31;
    const int b  = blockIdx.x;
    const int q0 = blockIdx.y * 64;
    const int q0w = (warp >> 1) * 16;
    const int wd  = warp & 1;
    const int cV  = wd * 3;

    {
        int hh = tid >> 6, q = tid & 63;
        sLinvf[tid] = g_Linv[(size_t)(b*H + hh)*S + q0 + q];
    }

    auto load_stage = [&](int jt, int hh, uint32_t bufb) {
        const int bhl = b*H + hh;
        const __nv_bfloat16* ehp = g_Eh + ((size_t)bhl*S + q0)*S + jt*128;
        const __nv_bfloat16* elp = g_El + ((size_t)bhl*S + q0)*S + jt*128;
        #pragma unroll
        for (int k = 0; k < 4; k++) {
            int idx = tid + k*256;
            int r = idx >> 4, cj = idx & 15;
            uint32_t off = r*256 + ((cj ^ (r&7))<<4);
            cp16(bufb + PM_EH + off, ehp + (size_t)r*S + cj*8);
            cp16(bufb + PM_EL + off, elp + (size_t)r*S + cj*8);
        }
        const __nv_bfloat16* vhp = g_vh + ((size_t)bhl*S + jt*128)*DH;
        const __nv_bfloat16* vlp = g_vl + ((size_t)bhl*S + jt*128)*DH;
        #pragma unroll
        for (int k = 0; k < 3; k++) {
            int idx = tid + k*256;
            int r = idx / 6, c = idx % 6;
            // permuted destination row (matches E's virtual j order)
            int vr = (r & 96) | (8*((r&7)>>1) + 2*((r>>3)&3) + (r&1));
            uint32_t off = vr*128 + ((c ^ (vr&7))<<4);
            cp16(bufb + PM_VH + off, vhp + r*DH + c*8);
            cp16(bufb + PM_VL + off, vlp + r*DH + c*8);
        }
    };

    load_stage(0, 0, sb + PM_OFF_TILE);
    cp_commit();
    __syncthreads();

    float acc[4][3][4];
    #pragma unroll
    for (int hh = 0; hh < 4; hh++)
        #pragma unroll
        for (int nt = 0; nt < 3; nt++)
            #pragma unroll
            for (int p = 0; p < 4; p++) acc[hh][nt][p] = 0.f;

    for (int jt = 0; jt < 16; jt++) {
        #pragma unroll
        for (int hh = 0; hh < 4; hh++) {
            const int st = jt*4 + hh;
            if (st + 1 < 64) {
                const int njt = (hh == 3) ? jt + 1 : jt;
                const int nhh = (hh == 3) ? 0 : hh + 1;
                load_stage(njt, nhh, sb + PM_OFF_TILE + ((st+1) & 1)*PM_BUF);
                cp_commit();
                cp_wait1();
            } else {
                cp_wait0();
            }
            __syncthreads();
            const uint32_t tb = sb + PM_OFF_TILE + (st & 1)*PM_BUF;
            const char*   tbp = smem + PM_OFF_TILE + (st & 1)*PM_BUF;

            // head-mean accumulation in VIRTUAL j order
            #pragma unroll
            for (int k = 0; k < 4; k++) {
                int idx = tid + k*256;
                int q = idx >> 4, cj = idx & 15;
                uint32_t eoff = q*256 + ((cj ^ (q&7))<<4);
                uint4 uh = *reinterpret_cast<const uint4*>(tbp + PM_EH + eoff);
                uint4 ul = *reinterpret_cast<const uint4*>(tbp + PM_EL + eoff);
                float linv = sLinvf[hh*64 + q];
                float2 f0 = __bfloat1622float2(*reinterpret_cast<__nv_bfloat162*>(&uh.x));
                float2 f1 = __bfloat1622float2(*reinterpret_cast<__nv_bfloat162*>(&uh.y));
                float2 f2 = __bfloat1622float2(*reinterpret_cast<__nv_bfloat162*>(&uh.z));
                float2 f3 = __bfloat1622float2(*reinterpret_cast<__nv_bfloat162*>(&uh.w));
                float2 g0 = __bfloat1622float2(*reinterpret_cast<__nv_bfloat162*>(&ul.x));
                float2 g1 = __bfloat1622float2(*reinterpret_cast<__nv_bfloat162*>(&ul.y));
                float2 g2 = __bfloat1622float2(*reinterpret_cast<__nv_bfloat162*>(&ul.z));
                float2 g3 = __bfloat1622float2(*reinterpret_cast<__nv_bfloat162*>(&ul.w));
                float* mp = sMean + q*132 + cj*8;
                if (hh == 0) {
                    float4 m0, m1;
                    m0.x = (f0.x+g0.x)*linv; m0.y = (f0.y+g0.y)*linv;
                    m0.z = (f1.x+g1.x)*linv; m0.w = (f1.y+g1.y)*linv;
                    m1.x = (f2.x+g2.x)*linv; m1.y = (f2.y+g2.y)*linv;
                    m1.z = (f3.x+g3.x)*linv; m1.w = (f3.y+g3.y)*linv;
                    *reinterpret_cast<float4*>(mp)     = m0;
                    *reinterpret_cast<float4*>(mp + 4) = m1;
                } else {
                    float4 m0 = *reinterpret_cast<float4*>(mp);
                    float4 m1 = *reinterpret_cast<float4*>(mp + 4);
                    m0.x += (f0.x+g0.x)*linv; m0.y += (f0.y+g0.y)*linv;
                    m0.z += (f1.x+g1.x)*linv; m0.w += (f1.y+g1.y)*linv;
                    m1.x += (f2.x+g2.x)*linv; m1.y += (f2.y+g2.y)*linv;
                    m1.z += (f3.x+g3.x)*linv; m1.w += (f3.y+g3.y)*linv;
                    *reinterpret_cast<float4*>(mp)     = m0;
                    *reinterpret_cast<float4*>(mp + 4) = m1;
                }
            }

            // MMA (virtual k-order on both sides)
            #pragma unroll
            for (int ks = 0; ks < 8; ks++) {
                int ra = q0w + (lane & 15);
                int ca = ks*2 + (lane >> 4);
                uint32_t aoff = ra*256 + ((ca ^ (ra&7))<<4);
                uint32_t ahf[4], alf[4];
                ldsm4(tb + PM_EH + aoff, ahf);
                ldsm4(tb + PM_EL + aoff, alf);

                int rb = ks*16 + (lane & 15);
                int cb4 = cV + (lane >> 4);
                uint32_t boff4 = rb*128 + ((cb4 ^ (rb&7))<<4);
                uint32_t bh4[4], bl4[4];
                ldsm4t(tb + PM_VH + boff4, bh4);
                ldsm4t(tb + PM_VL + boff4, bl4);
                int cb2 = cV + 2;
                uint32_t boff2 = rb*128 + ((cb2 ^ (rb&7))<<4);
                uint32_t bh2[2], bl2[2];
                ldsm2t(tb + PM_VH + boff2, bh2);
                ldsm2t(tb + PM_VL + boff2, bl2);

                #pragma unroll
                for (int nt = 0; nt < 2; nt++) {
                    float* a = acc[hh][nt];
                    mma16816(a, ahf, &bh4[nt*2]);
                    mma16816(a, ahf, &bl4[nt*2]);
                    mma16816(a, alf, &bh4[nt*2]);
                }
                {
                    float* a = acc[hh][2];
                    mma16816(a, ahf, bh2);
                    mma16816(a, ahf, bl2);
                    mma16816(a, alf, bh2);
                }
            }

            if (hh == 3) { // de-permuted mean write
                __syncthreads();
                #pragma unroll
                for (int k = 0; k < 8; k++) {
                    int idx = tid + k*256;
                    int q = idx >> 5, c4 = idx & 31;
                    int g = (c4 >> 3) << 5;
                    int r32 = (4*c4) & 31;
                    int v0 = g + 8*((r32 & 7) >> 1) + 2*(r32 >> 3);
                    float2 m0 = *reinterpret_cast<const float2*>(sMean + q*132 + v0);
                    float2 m1 = *reinterpret_cast<const float2*>(sMean + q*132 + v0 + 8);
                    float4 r;
                    r.x = 0.25f*m0.x; r.y = 0.25f*m0.y;
                    r.z = 0.25f*m1.x; r.w = 0.25f*m1.y;
                    *reinterpret_cast<float4*>(om + (size_t)(b*S + q0 + q)*S + jt*128 + c4*4) = r;
                }
            }
            __syncthreads();
        }
    }

    // epilogue: scale O frags by Linv, write ctx
    #pragma unroll
    for (int hh = 0; hh < 4; hh++) {
        const int row0 = q0w + (lane >> 2);
        const float l0 = sLinvf[hh*64 + row0];
        const float l1 = sLinvf[hh*64 + row0 + 8];
        #pragma unroll
        for (int nt = 0; nt < 3; nt++) {
            const int col = hh*48 + wd*24 + nt*8 + (lane & 3)*2;
            float2 o0; o0.x = acc[hh][nt][0]*l0; o0.y = acc[hh][nt][1]*l0;
            float2 o1; o1.x = acc[hh][nt][2]*l1; o1.y = acc[hh][nt][3]*l1;
            *reinterpret_cast<float2*>(g_ctx + (size_t)(b*S + q0 + row0)*D + col)     = o0;
            *reinterpret_cast<float2*>(g_ctx + (size_t)(b*S + q0 + row0 + 8)*D + col) = o1;
        }
    }
}

extern "C" void kernel_launch(void* const* d_in, const int* in_sizes, int n_in,
                              void* d_out, int out_size) {
    (void)in_sizes; (void)n_in; (void)out_size;
    const float* query = (const float*)d_in[0];
    const float* key   = (const float*)d_in[1];
    const float* value = (const float*)d_in[2];
    const int*   mask  = (const int*)  d_in[3];
    const float* bias  = (const float*)d_in[4];
    const float* Wq    = (const float*)d_in[5];
    const float* Wk    = (const float*)d_in[6];
    const float* Wv    = (const float*)d_in[7];
    const float* Wo    = (const float*)d_in[8];

    float* out = (float*)d_out;                 // [B,S,D]
    float* om  = out + B*S*D;                   // [B,S,S] mean weights

    float *pctx;
    cudaGetSymbolAddress((void**)&pctx, g_ctx);

    cudaFuncSetAttribute(logits_mma, cudaFuncAttributeMaxDynamicSharedMemorySize, SMEM_LG);
    cudaFuncSetAttribute(pv_mma,     cudaFuncAttributeMaxDynamicSharedMemorySize, SMEM_PV);

    transpose_w<<<dim3(6,6,4), dim3(32,8)>>>(Wq, Wk, Wv, Wo);
    proj3_kernel<<<dim3(256,3), 128>>>(query, key, value);
    logits_mma<<<dim3(B*H, S/64), 256, SMEM_LG>>>(mask, bias);
    pv_mma<<<dim3(B, S/64), 256, SMEM_PV>>>(om);
    proj1_kernel<<<dim3(256,1), 128>>>(pctx, out);
}